// round 16
// baseline (speedup 1.0000x reference)
#include <cuda_runtime.h>
#include <math.h>

#define Bsz    16
#define Sd     4096
#define Hd     2048
#define POOLD  4096
#define SPLITS 64
#define ROWS   64                     // rows per main-pass block
#define NB     16                     // batches of 4 rows
#define SCALE  0.022097086912079608f  // 1/sqrt(2048)
#define EPSV   1e-6f

// ---------------- scratch ----------------
__device__ float g_q[Hd];
__device__ float g_qk[Hd];
__device__ float g_pm[Bsz * SPLITS];
__device__ float g_pl[Bsz * SPLITS];
__device__ float g_pacc[Bsz * SPLITS * Hd];   // 8.4 MB
__device__ float g_xp[Bsz * Hd];
__device__ float g_pooled[Bsz * Hd];
__device__ float g_normed[Bsz * Hd];

// ---------------- 0. zero init (atomic targets) ----------------
__global__ void zero_kernel(float* __restrict__ out) {
    int i = blockIdx.x * 256 + threadIdx.x;   // 65536 threads
    if (i < Hd)        g_qk[i] = 0.f;
    if (i < Bsz * Hd)  g_pooled[i] = 0.f;
    out[i] = 0.f;
}

// ---------------- 1. q[d] = dot(Wq[d,:], lq) ----------------
__global__ void qproj_kernel(const float* __restrict__ Wq,
                             const float* __restrict__ lq) {
    int d    = blockIdx.x * 8 + (threadIdx.x >> 5);
    int lane = threadIdx.x & 31;
    const float4* r4 = (const float4*)(Wq + (size_t)d * Hd);
    const float4* v4 = (const float4*)lq;
    float s0 = 0.f, s1 = 0.f;
#pragma unroll
    for (int i = 0; i < 16; i += 2) {
        float4 a = r4[lane + 32 * i];
        float4 b = v4[lane + 32 * i];
        s0 += a.x * b.x + a.y * b.y + a.z * b.z + a.w * b.w;
        a = r4[lane + 32 * (i + 1)];
        b = v4[lane + 32 * (i + 1)];
        s1 += a.x * b.x + a.y * b.y + a.z * b.z + a.w * b.w;
    }
    float s = s0 + s1;
#pragma unroll
    for (int o = 16; o; o >>= 1) s += __shfl_xor_sync(0xffffffffu, s, o);
    if (lane == 0) g_q[d] = s;
}

// ---------------- 2. qk[h] += sum_d Wk[d,h] * q[d]   (split-d + atomics) ----------------
__global__ void kproj_kernel(const float* __restrict__ Wk) {
    int h  = blockIdx.x * 256 + threadIdx.x;
    int d0 = blockIdx.y * 64;
    float a0 = 0.f, a1 = 0.f;
#pragma unroll 8
    for (int d = 0; d < 64; d += 2) {
        a0 += Wk[(size_t)(d0 + d) * Hd + h] * g_q[d0 + d];
        a1 += Wk[(size_t)(d0 + d + 1) * Hd + h] * g_q[d0 + d + 1];
    }
    atomicAdd(&g_qk[h], a0 + a1);
}

// ---------------- 3. main flash pass (H-split, qk register-hoisted) ----------------
// grid = (SPLITS, Bsz), 256 threads = 8 warps; warp w owns H-chunk [w*256, w*256+256)
// for ALL 64 rows. qk operands are per-thread constants -> 2 float4 registers,
// loaded once from global (no smem qk at all).
__global__ void __launch_bounds__(256, 3)
main_pass(const float* __restrict__ X, const int* __restrict__ mask) {
    __shared__ float s_dot[2][4][8];      // [parity][row-in-batch][warp]
    __shared__ unsigned s_mask[2];
    int b = blockIdx.y, sp = blockIdx.x;
    int t = threadIdx.x, lane = t & 31, warp = t >> 5;
    int base = warp * 64 + lane;          // this thread's first float4 index in a row

    // per-thread constant qk operands (coalesced global read, L2-cached)
    const float4* qk4 = (const float4*)g_qk;
    float4 qa = qk4[base];
    float4 qb = qk4[base + 32];

    if (warp < 2) {                       // 64 mask words -> 2 ballot words
        int v = mask[(size_t)b * Sd + sp * ROWS + warp * 32 + lane];
        unsigned bits = __ballot_sync(0xffffffffu, v != 0);
        if (lane == 0) s_mask[warp] = bits;
    }
    __syncthreads();
    unsigned mk0 = s_mask[0], mk1 = s_mask[1];

    const float4* X4 = (const float4*)(X + ((size_t)b * Sd + (size_t)sp * ROWS) * Hd);

    float m = -INFINITY, l = 0.f;
    float4 a0 = make_float4(0.f, 0.f, 0.f, 0.f);
    float4 a1 = make_float4(0.f, 0.f, 0.f, 0.f);
    float4 xa[4], xb[4];
#pragma unroll
    for (int j = 0; j < 4; j++) { xa[j] = a0; xb[j] = a0; }   // finite init (NaN safety)

    for (int bi = 0; bi < NB; bi++) {
        unsigned mb = (bi < 8) ? (mk0 >> (4 * bi)) : (mk1 >> (4 * bi - 32));
        int par = bi & 1;
        float pd[4];
#pragma unroll
        for (int j = 0; j < 4; j++) {
            if ((mb >> j) & 1u) {         // masked row: keep stale (finite) x, p2 will be 0
                const float4* xr = X4 + (size_t)(4 * bi + j) * 512 + base;
                xa[j] = xr[0];
                xb[j] = xr[32];
            }
        }
#pragma unroll
        for (int j = 0; j < 4; j++) {
            pd[j] = xa[j].x * qa.x + xa[j].y * qa.y + xa[j].z * qa.z + xa[j].w * qa.w
                  + xb[j].x * qb.x + xb[j].y * qb.y + xb[j].z * qb.z + xb[j].w * qb.w;
        }
#pragma unroll
        for (int o = 16; o; o >>= 1) {    // 4 interleaved warp reductions
            pd[0] += __shfl_xor_sync(0xffffffffu, pd[0], o);
            pd[1] += __shfl_xor_sync(0xffffffffu, pd[1], o);
            pd[2] += __shfl_xor_sync(0xffffffffu, pd[2], o);
            pd[3] += __shfl_xor_sync(0xffffffffu, pd[3], o);
        }
        if (lane == 0) {
            s_dot[par][0][warp] = pd[0];
            s_dot[par][1][warp] = pd[1];
            s_dot[par][2][warp] = pd[2];
            s_dot[par][3][warp] = pd[3];
        }
        __syncthreads();                  // parity-2 buffering makes 1 sync/batch safe
#pragma unroll
        for (int j = 0; j < 4; j++) {
            if (!((mb >> j) & 1u)) continue;
            float sc = 0.f;
#pragma unroll
            for (int w = 0; w < 8; w++) sc += s_dot[par][j][w];   // broadcast LDS, deterministic
            sc *= SCALE;
            if (sc > m) {
                float c = __expf(m - sc); // exact 0 on first active row
                l *= c;
                a0.x *= c; a0.y *= c; a0.z *= c; a0.w *= c;
                a1.x *= c; a1.y *= c; a1.z *= c; a1.w *= c;
                m = sc;
            }
            float p2 = __expf(sc - m);
            l += p2;
            a0.x += p2 * xa[j].x; a0.y += p2 * xa[j].y;
            a0.z += p2 * xa[j].z; a0.w += p2 * xa[j].w;
            a1.x += p2 * xb[j].x; a1.y += p2 * xb[j].y;
            a1.z += p2 * xb[j].z; a1.w += p2 * xb[j].w;
        }
    }

    // (m, l) identical across all threads; no merge needed.
    if (t == 0) {
        g_pm[b * SPLITS + sp] = m;
        g_pl[b * SPLITS + sp] = l;
    }
    float4* pa = (float4*)(g_pacc + (size_t)(b * SPLITS + sp) * Hd);
    pa[base] = a0;
    pa[base + 32] = a1;
}

// ---------------- 4. combine partials -> xp (2 outputs/thread, 16 loads in flight) ----------------
// grid = (Bsz, 8), 256 threads. Block covers 64 float4 indices; group grp
// (0..7) of 32 threads sums splits [grp*8, grp*8+8) for 2 indices each.
__global__ void combine_kernel() {
    __shared__ float s_ew[SPLITS];
    __shared__ float s_inv;
    __shared__ float4 s_part[7][64];
    int b = blockIdx.x;
    int t = threadIdx.x;
    if (t < 32) {
        float m0 = g_pm[b * SPLITS + t];
        float m1 = g_pm[b * SPLITS + 32 + t];
        float M = fmaxf(m0, m1);
#pragma unroll
        for (int o = 16; o; o >>= 1) M = fmaxf(M, __shfl_xor_sync(0xffffffffu, M, o));
        float e0 = (m0 == -INFINITY) ? 0.f : __expf(m0 - M);
        float e1 = (m1 == -INFINITY) ? 0.f : __expf(m1 - M);
        float s = g_pl[b * SPLITS + t] * e0 + g_pl[b * SPLITS + 32 + t] * e1;
#pragma unroll
        for (int o = 16; o; o >>= 1) s += __shfl_xor_sync(0xffffffffu, s, o);
        s_ew[t] = e0;
        s_ew[t + 32] = e1;
        if (t == 0) s_inv = 1.f / s;
    }
    __syncthreads();

    int li  = t & 31;                      // local float4 index (first of two)
    int grp = t >> 5;                      // split group 0..7
    int idx0 = blockIdx.y * 64 + li;       // float4 index in [0,512)
    int idx1 = idx0 + 32;

    float4 s0 = make_float4(0.f, 0.f, 0.f, 0.f);
    float4 s1 = make_float4(0.f, 0.f, 0.f, 0.f);
    const float4* pa = (const float4*)g_pacc;
#pragma unroll
    for (int i = 0; i < 8; i++) {          // 16 independent loads in flight
        int spl = grp * 8 + i;
        float e = s_ew[spl];
        float4 v = pa[(size_t)(b * SPLITS + spl) * 512 + idx0];
        s0.x += e * v.x; s0.y += e * v.y; s0.z += e * v.z; s0.w += e * v.w;
        v = pa[(size_t)(b * SPLITS + spl) * 512 + idx1];
        s1.x += e * v.x; s1.y += e * v.y; s1.z += e * v.z; s1.w += e * v.w;
    }
    if (grp) { s_part[grp - 1][li] = s0; s_part[grp - 1][li + 32] = s1; }
    __syncthreads();
    if (grp == 0) {
        float inv = s_inv;
#pragma unroll
        for (int g = 0; g < 7; g++) {
            float4 p = s_part[g][li];
            s0.x += p.x; s0.y += p.y; s0.z += p.z; s0.w += p.w;
            p = s_part[g][li + 32];
            s1.x += p.x; s1.y += p.y; s1.z += p.z; s1.w += p.w;
        }
        s0.x *= inv; s0.y *= inv; s0.z *= inv; s0.w *= inv;
        s1.x *= inv; s1.y *= inv; s1.z *= inv; s1.w *= inv;
        float4* xp4 = (float4*)(g_xp + (size_t)b * Hd);
        xp4[idx0] = s0;
        xp4[idx1] = s1;
    }
}

// ---------------- 5./7. skinny GEMM: out[b,d] += sum_k W[d,k]*xin[b,k] ----------------
__global__ void skinny_gemm(const float* __restrict__ W, int mode,
                            float* __restrict__ dout, int D, int K) {
    __shared__ float ws[64][65];
    __shared__ float xs[16][65];
    const float* xin = (mode == 0) ? g_xp : g_normed;
    float* out       = (mode == 0) ? g_pooled : dout;

    int t  = threadIdx.x;
    int d0 = blockIdx.x * 64;
    int kchunk = K / gridDim.y;
    int k0 = blockIdx.y * kchunk;
    int b0 = (t & 7) * 2;
    int dg = t >> 3;

    float acc[4][2] = {{0.f,0.f},{0.f,0.f},{0.f,0.f},{0.f,0.f}};

    for (int kc = k0; kc < k0 + kchunk; kc += 64) {
        for (int i = t; i < 1024; i += 128) {
            int row = i >> 4, c4 = i & 15;
            float4 v = *(const float4*)&W[(size_t)(d0 + row) * K + kc + c4 * 4];
            ws[row][c4 * 4 + 0] = v.x; ws[row][c4 * 4 + 1] = v.y;
            ws[row][c4 * 4 + 2] = v.z; ws[row][c4 * 4 + 3] = v.w;
        }
        for (int i = t; i < 256; i += 128) {
            int row = i >> 4, c4 = i & 15;
            float4 v = *(const float4*)&xin[(size_t)row * K + kc + c4 * 4];
            xs[row][c4 * 4 + 0] = v.x; xs[row][c4 * 4 + 1] = v.y;
            xs[row][c4 * 4 + 2] = v.z; xs[row][c4 * 4 + 3] = v.w;
        }
        __syncthreads();
#pragma unroll 8
        for (int kt = 0; kt < 64; kt++) {
            float x0 = xs[b0][kt], x1 = xs[b0 + 1][kt];
#pragma unroll
            for (int r = 0; r < 4; r++) {
                float w = ws[dg * 4 + r][kt];
                acc[r][0] += w * x0;
                acc[r][1] += w * x1;
            }
        }
        __syncthreads();
    }
#pragma unroll
    for (int r = 0; r < 4; r++) {
        atomicAdd(&out[(size_t)(b0 + 0) * D + d0 + dg * 4 + r], acc[r][0]);
        atomicAdd(&out[(size_t)(b0 + 1) * D + d0 + dg * 4 + r], acc[r][1]);
    }
}

// ---------------- 6. rmsnorm ----------------
__global__ void rmsnorm_kernel(const float* __restrict__ nw) {
    __shared__ float red[8];
    __shared__ float sv;
    int b = blockIdx.x, t = threadIdx.x, lane = t & 31, warp = t >> 5;
    const float4* p4 = (const float4*)(g_pooled + (size_t)b * Hd);
    float4 v0 = p4[t], v1 = p4[t + 256];
    float ss = v0.x*v0.x + v0.y*v0.y + v0.z*v0.z + v0.w*v0.w
             + v1.x*v1.x + v1.y*v1.y + v1.z*v1.z + v1.w*v1.w;
#pragma unroll
    for (int o = 16; o; o >>= 1) ss += __shfl_xor_sync(0xffffffffu, ss, o);
    if (lane == 0) red[warp] = ss;
    __syncthreads();
    if (t == 0) {
        float s = 0.f;
#pragma unroll
        for (int w = 0; w < 8; w++) s += red[w];
        sv = rsqrtf(s / (float)Hd + EPSV);
    }
    __syncthreads();
    float rs = sv;
    const float4* w4 = (const float4*)nw;
    float4* n4 = (float4*)(g_normed + (size_t)b * Hd);
    float4 wa = w4[t], wb = w4[t + 256];
    float4 o0, o1;
    o0.x = v0.x * rs * wa.x; o0.y = v0.y * rs * wa.y;
    o0.z = v0.z * rs * wa.z; o0.w = v0.w * rs * wa.w;
    o1.x = v1.x * rs * wb.x; o1.y = v1.y * rs * wb.y;
    o1.z = v1.z * rs * wb.z; o1.w = v1.w * rs * wb.w;
    n4[t] = o0;
    n4[t + 256] = o1;
}

// ---------------- launch ----------------
extern "C" void kernel_launch(void* const* d_in, const int* in_sizes, int n_in,
                              void* d_out, int out_size) {
    const float* X  = (const float*)d_in[0];
    const int*   mk = (const int*)d_in[1];
    const float* lq = (const float*)d_in[2];
    const float* Wq = (const float*)d_in[3];
    const float* Wk = (const float*)d_in[4];
    const float* Wv = (const float*)d_in[5];
    const float* Wo = (const float*)d_in[6];
    const float* nw = (const float*)d_in[7];
    float* out = (float*)d_out;

    zero_kernel<<<256, 256>>>(out);                          // zero atomic targets
    qproj_kernel<<<Hd / 8, 256>>>(Wq, lq);                   // q = Wq @ lq
    kproj_kernel<<<dim3(Hd / 256, 32), 256>>>(Wk);           // qk = Wk^T q
    main_pass<<<dim3(SPLITS, Bsz), 256>>>(X, mk);            // online softmax (4th -> profiled)
    combine_kernel<<<dim3(Bsz, 8), 256>>>();                 // stats + merge splits -> xp
    skinny_gemm<<<dim3(Hd / 64, 16), 128>>>(Wv, 0, out, Hd, Hd);       // pooled = xp @ Wv^T
    rmsnorm_kernel<<<Bsz, 256>>>(nw);                        // normed
    skinny_gemm<<<dim3(POOLD / 64, 16), 128>>>(Wo, 1, out, POOLD, Hd); // out = normed @ Wo^T
}

// round 17
// speedup vs baseline: 1.0918x; 1.0918x over previous
#include <cuda_runtime.h>
#include <math.h>

#define Bsz    16
#define Sd     4096
#define Hd     2048
#define POOLD  4096
#define SPLITS 64
#define ROWS   64                     // rows per main-pass block
#define NB     16                     // batches of 4 rows
#define SCALE  0.022097086912079608f  // 1/sqrt(2048)
#define EPSV   1e-6f

// ---------------- scratch ----------------
__device__ float g_q[Hd];
__device__ float g_qk[Hd];
__device__ float g_pm[Bsz * SPLITS];
__device__ float g_pl[Bsz * SPLITS];
__device__ float g_pacc[Bsz * SPLITS * Hd];   // 8.4 MB
__device__ float g_xp[Bsz * Hd];
__device__ float g_pooled[Bsz * Hd];
__device__ float g_normed[Bsz * Hd];

// ---------------- 0. zero init (atomic targets) ----------------
__global__ void zero_kernel(float* __restrict__ out) {
    int i = blockIdx.x * 256 + threadIdx.x;   // 65536 threads
    if (i < Hd)        g_qk[i] = 0.f;
    if (i < Bsz * Hd)  g_pooled[i] = 0.f;
    out[i] = 0.f;
}

// ---------------- 1. q[d] = dot(Wq[d,:], lq) ----------------
__global__ void qproj_kernel(const float* __restrict__ Wq,
                             const float* __restrict__ lq) {
    int d    = blockIdx.x * 8 + (threadIdx.x >> 5);
    int lane = threadIdx.x & 31;
    const float4* r4 = (const float4*)(Wq + (size_t)d * Hd);
    const float4* v4 = (const float4*)lq;
    float s0 = 0.f, s1 = 0.f;
#pragma unroll
    for (int i = 0; i < 16; i += 2) {
        float4 a = r4[lane + 32 * i];
        float4 b = v4[lane + 32 * i];
        s0 += a.x * b.x + a.y * b.y + a.z * b.z + a.w * b.w;
        a = r4[lane + 32 * (i + 1)];
        b = v4[lane + 32 * (i + 1)];
        s1 += a.x * b.x + a.y * b.y + a.z * b.z + a.w * b.w;
    }
    float s = s0 + s1;
#pragma unroll
    for (int o = 16; o; o >>= 1) s += __shfl_xor_sync(0xffffffffu, s, o);
    if (lane == 0) g_q[d] = s;
}

// ---------------- 2. qk[h] += sum_d Wk[d,h] * q[d]   (split-d + atomics, ILP-4) ----------------
__global__ void kproj_kernel(const float* __restrict__ Wk) {
    int h  = blockIdx.x * 256 + threadIdx.x;
    int d0 = blockIdx.y * 64;
    float a0 = 0.f, a1 = 0.f, a2 = 0.f, a3 = 0.f;
#pragma unroll 4
    for (int d = 0; d < 64; d += 4) {
        a0 += Wk[(size_t)(d0 + d) * Hd + h] * g_q[d0 + d];
        a1 += Wk[(size_t)(d0 + d + 1) * Hd + h] * g_q[d0 + d + 1];
        a2 += Wk[(size_t)(d0 + d + 2) * Hd + h] * g_q[d0 + d + 2];
        a3 += Wk[(size_t)(d0 + d + 3) * Hd + h] * g_q[d0 + d + 3];
    }
    atomicAdd(&g_qk[h], (a0 + a1) + (a2 + a3));
}

// ---------------- 3. main flash pass (H-split across 8 warps, 4-row batches) ----------------
// R15 version verbatim — measured optimum (55.4 us, 5.0 TB/s).
// grid = (SPLITS, Bsz), 256 threads = 8 warps; warp w owns H-chunk [w*256, w*256+256)
// for ALL 64 rows. One __syncthreads per 4-row batch (parity double-buffered dots).
__global__ void __launch_bounds__(256, 3)
main_pass(const float* __restrict__ X, const int* __restrict__ mask) {
    __shared__ float4 s_qk[512];          // 8 KB
    __shared__ float s_dot[2][4][8];      // [parity][row-in-batch][warp]
    __shared__ unsigned s_mask[2];
    int b = blockIdx.y, sp = blockIdx.x;
    int t = threadIdx.x, lane = t & 31, warp = t >> 5;
    int base = warp * 64 + lane;          // this thread's first float4 index in a row

    const float4* qk4 = (const float4*)g_qk;
    for (int i = t; i < 512; i += 256) s_qk[i] = qk4[i];

    if (warp < 2) {                       // 64 mask words -> 2 ballot words
        int v = mask[(size_t)b * Sd + sp * ROWS + warp * 32 + lane];
        unsigned bits = __ballot_sync(0xffffffffu, v != 0);
        if (lane == 0) s_mask[warp] = bits;
    }
    __syncthreads();
    unsigned mk0 = s_mask[0], mk1 = s_mask[1];

    const float4* X4 = (const float4*)(X + ((size_t)b * Sd + (size_t)sp * ROWS) * Hd);

    float m = -INFINITY, l = 0.f;
    float4 a0 = make_float4(0.f, 0.f, 0.f, 0.f);
    float4 a1 = make_float4(0.f, 0.f, 0.f, 0.f);
    float4 xa[4], xb[4];
#pragma unroll
    for (int j = 0; j < 4; j++) { xa[j] = a0; xb[j] = a0; }   // finite init (NaN safety)

    for (int bi = 0; bi < NB; bi++) {
        unsigned mb = (bi < 8) ? (mk0 >> (4 * bi)) : (mk1 >> (4 * bi - 32));
        int par = bi & 1;
        float pd[4];
#pragma unroll
        for (int j = 0; j < 4; j++) {
            if ((mb >> j) & 1u) {         // masked row: keep stale (finite) x, p2 will be 0
                const float4* xr = X4 + (size_t)(4 * bi + j) * 512 + base;
                xa[j] = xr[0];
                xb[j] = xr[32];
            }
        }
#pragma unroll
        for (int j = 0; j < 4; j++) {
            float4 qa = s_qk[base], qb = s_qk[base + 32];
            pd[j] = xa[j].x * qa.x + xa[j].y * qa.y + xa[j].z * qa.z + xa[j].w * qa.w
                  + xb[j].x * qb.x + xb[j].y * qb.y + xb[j].z * qb.z + xb[j].w * qb.w;
        }
#pragma unroll
        for (int o = 16; o; o >>= 1) {    // 4 interleaved warp reductions
            pd[0] += __shfl_xor_sync(0xffffffffu, pd[0], o);
            pd[1] += __shfl_xor_sync(0xffffffffu, pd[1], o);
            pd[2] += __shfl_xor_sync(0xffffffffu, pd[2], o);
            pd[3] += __shfl_xor_sync(0xffffffffu, pd[3], o);
        }
        if (lane == 0) {
            s_dot[par][0][warp] = pd[0];
            s_dot[par][1][warp] = pd[1];
            s_dot[par][2][warp] = pd[2];
            s_dot[par][3][warp] = pd[3];
        }
        __syncthreads();                  // parity-2 buffering makes 1 sync/batch safe
#pragma unroll
        for (int j = 0; j < 4; j++) {
            if (!((mb >> j) & 1u)) continue;
            float sc = 0.f;
#pragma unroll
            for (int w = 0; w < 8; w++) sc += s_dot[par][j][w];   // broadcast LDS, deterministic
            sc *= SCALE;
            if (sc > m) {
                float c = __expf(m - sc); // exact 0 on first active row
                l *= c;
                a0.x *= c; a0.y *= c; a0.z *= c; a0.w *= c;
                a1.x *= c; a1.y *= c; a1.z *= c; a1.w *= c;
                m = sc;
            }
            float p2 = __expf(sc - m);
            l += p2;
            a0.x += p2 * xa[j].x; a0.y += p2 * xa[j].y;
            a0.z += p2 * xa[j].z; a0.w += p2 * xa[j].w;
            a1.x += p2 * xb[j].x; a1.y += p2 * xb[j].y;
            a1.z += p2 * xb[j].z; a1.w += p2 * xb[j].w;
        }
    }

    // (m, l) identical across all threads; no merge needed.
    if (t == 0) {
        g_pm[b * SPLITS + sp] = m;
        g_pl[b * SPLITS + sp] = l;
    }
    float4* pa = (float4*)(g_pacc + (size_t)(b * SPLITS + sp) * Hd);
    pa[base] = a0;
    pa[base + 32] = a1;
}

// ---------------- 4. combine partials -> xp (2 outputs/thread, 16 loads in flight) ----------------
// grid = (Bsz, 8), 256 threads. Block covers 64 float4 indices; group grp
// (0..7) of 32 threads sums splits [grp*8, grp*8+8) for 2 indices each.
__global__ void combine_kernel() {
    __shared__ float s_ew[SPLITS];
    __shared__ float s_inv;
    __shared__ float4 s_part[7][64];
    int b = blockIdx.x;
    int t = threadIdx.x;
    if (t < 32) {
        float m0 = g_pm[b * SPLITS + t];
        float m1 = g_pm[b * SPLITS + 32 + t];
        float M = fmaxf(m0, m1);
#pragma unroll
        for (int o = 16; o; o >>= 1) M = fmaxf(M, __shfl_xor_sync(0xffffffffu, M, o));
        float e0 = (m0 == -INFINITY) ? 0.f : __expf(m0 - M);
        float e1 = (m1 == -INFINITY) ? 0.f : __expf(m1 - M);
        float s = g_pl[b * SPLITS + t] * e0 + g_pl[b * SPLITS + 32 + t] * e1;
#pragma unroll
        for (int o = 16; o; o >>= 1) s += __shfl_xor_sync(0xffffffffu, s, o);
        s_ew[t] = e0;
        s_ew[t + 32] = e1;
        if (t == 0) s_inv = 1.f / s;
    }
    __syncthreads();

    int li  = t & 31;                      // local float4 index (first of two)
    int grp = t >> 5;                      // split group 0..7
    int idx0 = blockIdx.y * 64 + li;       // float4 index in [0,512)
    int idx1 = idx0 + 32;

    float4 s0 = make_float4(0.f, 0.f, 0.f, 0.f);
    float4 s1 = make_float4(0.f, 0.f, 0.f, 0.f);
    const float4* pa = (const float4*)g_pacc;
#pragma unroll
    for (int i = 0; i < 8; i++) {          // 16 independent loads in flight
        int spl = grp * 8 + i;
        float e = s_ew[spl];
        float4 v = pa[(size_t)(b * SPLITS + spl) * 512 + idx0];
        s0.x += e * v.x; s0.y += e * v.y; s0.z += e * v.z; s0.w += e * v.w;
        v = pa[(size_t)(b * SPLITS + spl) * 512 + idx1];
        s1.x += e * v.x; s1.y += e * v.y; s1.z += e * v.z; s1.w += e * v.w;
    }
    if (grp) { s_part[grp - 1][li] = s0; s_part[grp - 1][li + 32] = s1; }
    __syncthreads();
    if (grp == 0) {
        float inv = s_inv;
#pragma unroll
        for (int g = 0; g < 7; g++) {
            float4 p = s_part[g][li];
            s0.x += p.x; s0.y += p.y; s0.z += p.z; s0.w += p.w;
            p = s_part[g][li + 32];
            s1.x += p.x; s1.y += p.y; s1.z += p.z; s1.w += p.w;
        }
        s0.x *= inv; s0.y *= inv; s0.z *= inv; s0.w *= inv;
        s1.x *= inv; s1.y *= inv; s1.z *= inv; s1.w *= inv;
        float4* xp4 = (float4*)(g_xp + (size_t)b * Hd);
        xp4[idx0] = s0;
        xp4[idx1] = s1;
    }
}

// ---------------- 5./7. skinny GEMM: out[b,d] += sum_k W[d,k]*xin[b,k] ----------------
__global__ void skinny_gemm(const float* __restrict__ W, int mode,
                            float* __restrict__ dout, int D, int K) {
    __shared__ float ws[64][65];
    __shared__ float xs[16][65];
    const float* xin = (mode == 0) ? g_xp : g_normed;
    float* out       = (mode == 0) ? g_pooled : dout;

    int t  = threadIdx.x;
    int d0 = blockIdx.x * 64;
    int kchunk = K / gridDim.y;
    int k0 = blockIdx.y * kchunk;
    int b0 = (t & 7) * 2;
    int dg = t >> 3;

    float acc[4][2] = {{0.f,0.f},{0.f,0.f},{0.f,0.f},{0.f,0.f}};

    for (int kc = k0; kc < k0 + kchunk; kc += 64) {
        for (int i = t; i < 1024; i += 128) {
            int row = i >> 4, c4 = i & 15;
            float4 v = *(const float4*)&W[(size_t)(d0 + row) * K + kc + c4 * 4];
            ws[row][c4 * 4 + 0] = v.x; ws[row][c4 * 4 + 1] = v.y;
            ws[row][c4 * 4 + 2] = v.z; ws[row][c4 * 4 + 3] = v.w;
        }
        for (int i = t; i < 256; i += 128) {
            int row = i >> 4, c4 = i & 15;
            float4 v = *(const float4*)&xin[(size_t)row * K + kc + c4 * 4];
            xs[row][c4 * 4 + 0] = v.x; xs[row][c4 * 4 + 1] = v.y;
            xs[row][c4 * 4 + 2] = v.z; xs[row][c4 * 4 + 3] = v.w;
        }
        __syncthreads();
#pragma unroll 8
        for (int kt = 0; kt < 64; kt++) {
            float x0 = xs[b0][kt], x1 = xs[b0 + 1][kt];
#pragma unroll
            for (int r = 0; r < 4; r++) {
                float w = ws[dg * 4 + r][kt];
                acc[r][0] += w * x0;
                acc[r][1] += w * x1;
            }
        }
        __syncthreads();
    }
#pragma unroll
    for (int r = 0; r < 4; r++) {
        atomicAdd(&out[(size_t)(b0 + 0) * D + d0 + dg * 4 + r], acc[r][0]);
        atomicAdd(&out[(size_t)(b0 + 1) * D + d0 + dg * 4 + r], acc[r][1]);
    }
}

// ---------------- 6. rmsnorm ----------------
__global__ void rmsnorm_kernel(const float* __restrict__ nw) {
    __shared__ float red[8];
    __shared__ float sv;
    int b = blockIdx.x, t = threadIdx.x, lane = t & 31, warp = t >> 5;
    const float4* p4 = (const float4*)(g_pooled + (size_t)b * Hd);
    float4 v0 = p4[t], v1 = p4[t + 256];
    float ss = v0.x*v0.x + v0.y*v0.y + v0.z*v0.z + v0.w*v0.w
             + v1.x*v1.x + v1.y*v1.y + v1.z*v1.z + v1.w*v1.w;
#pragma unroll
    for (int o = 16; o; o >>= 1) ss += __shfl_xor_sync(0xffffffffu, ss, o);
    if (lane == 0) red[warp] = ss;
    __syncthreads();
    if (t == 0) {
        float s = 0.f;
#pragma unroll
        for (int w = 0; w < 8; w++) s += red[w];
        sv = rsqrtf(s / (float)Hd + EPSV);
    }
    __syncthreads();
    float rs = sv;
    const float4* w4 = (const float4*)nw;
    float4* n4 = (float4*)(g_normed + (size_t)b * Hd);
    float4 wa = w4[t], wb = w4[t + 256];
    float4 o0, o1;
    o0.x = v0.x * rs * wa.x; o0.y = v0.y * rs * wa.y;
    o0.z = v0.z * rs * wa.z; o0.w = v0.w * rs * wa.w;
    o1.x = v1.x * rs * wb.x; o1.y = v1.y * rs * wb.y;
    o1.z = v1.z * rs * wb.z; o1.w = v1.w * rs * wb.w;
    n4[t] = o0;
    n4[t + 256] = o1;
}

// ---------------- launch ----------------
extern "C" void kernel_launch(void* const* d_in, const int* in_sizes, int n_in,
                              void* d_out, int out_size) {
    const float* X  = (const float*)d_in[0];
    const int*   mk = (const int*)d_in[1];
    const float* lq = (const float*)d_in[2];
    const float* Wq = (const float*)d_in[3];
    const float* Wk = (const float*)d_in[4];
    const float* Wv = (const float*)d_in[5];
    const float* Wo = (const float*)d_in[6];
    const float* nw = (const float*)d_in[7];
    float* out = (float*)d_out;

    zero_kernel<<<256, 256>>>(out);                          // zero atomic targets
    qproj_kernel<<<Hd / 8, 256>>>(Wq, lq);                   // q = Wq @ lq
    kproj_kernel<<<dim3(Hd / 256, 32), 256>>>(Wk);           // qk = Wk^T q
    main_pass<<<dim3(SPLITS, Bsz), 256>>>(X, mk);            // online softmax (4th -> profiled)
    combine_kernel<<<dim3(Bsz, 8), 256>>>();                 // stats + merge splits -> xp
    skinny_gemm<<<dim3(Hd / 64, 16), 128>>>(Wv, 0, out, Hd, Hd);       // pooled = xp @ Wv^T
    rmsnorm_kernel<<<Bsz, 256>>>(nw);                        // normed
    skinny_gemm<<<dim3(POOLD / 64, 16), 128>>>(Wo, 1, out, POOLD, Hd); // out = normed @ Wo^T
}